// round 4
// baseline (speedup 1.0000x reference)
#include <cuda_runtime.h>
#include <cstdint>

#define B_  64
#define S_  2048
#define D_  256
#define V_  256
#define L_  4
#define M_  (B_*S_)      // 131072
#define G3  (3*D_)       // 768

// ---------------- scratch (device globals; allocation-free) ----------------
__device__ __align__(16) float g_seqA[(size_t)M_*D_];
__device__ __align__(16) float g_seqB[(size_t)M_*D_];
__device__ __align__(16) float g_gi  [(size_t)M_*G3];
__device__ __align__(16) float g_hbuf[2*B_*D_];
__device__ int   g_ctr[16];

typedef unsigned long long u64;

__device__ __forceinline__ u64 pk(float x, float y){
    u64 r; asm("mov.b64 %0,{%1,%2};" : "=l"(r) : "f"(x), "f"(y)); return r;
}
__device__ __forceinline__ void fma2(u64 &a, u64 b, u64 c){
    asm("fma.rn.f32x2 %0,%1,%2,%0;" : "+l"(a) : "l"(b), "l"(c));
}
__device__ __forceinline__ float2 up(u64 v){
    float2 f; asm("mov.b64 {%0,%1},%2;" : "=f"(f.x), "=f"(f.y) : "l"(v)); return f;
}

// ---------------- embedding gather ----------------
__global__ void embed_k(const int* __restrict__ x, const float* __restrict__ emb){
    int t = blockIdx.x*256 + threadIdx.x;          // float4 index over M_*64
    int m = t >> 6, d4 = t & 63;
    int tok = __ldg(&x[m]);
    ((float4*)g_seqA)[(size_t)m*64 + d4] = ((const float4*)emb)[(size_t)tok*64 + d4];
}

// ---------------- C[M,N] = A[M,256] * Bw[N,256]^T + bias ----------------
// asel: 0 -> g_seqA, 1 -> g_seqB.  csel: 0 -> g_gi, 1 -> Cext.
__global__ __launch_bounds__(256,2)
void gemm_tn(int asel, const float* __restrict__ Bw, const float* __restrict__ bias,
             float* __restrict__ Cext, int csel, int N){
    __shared__ float As[16][128];
    __shared__ float Bs[16][128];
    const float* A = asel ? g_seqB : g_seqA;
    float*       C = csel ? Cext  : g_gi;

    const int nt = N >> 7;
    const int by = blockIdx.x / nt, bx = blockIdx.x % nt;
    const int m0 = by << 7, n0 = bx << 7;
    const int t  = threadIdx.x, tx = t & 15, ty = t >> 4;
    const int lr = t >> 2, lc = (t & 3) << 2;

    const float* Ap = A  + (size_t)(m0 + lr)*256 + lc;
    const float* Bp = Bw + (size_t)(n0 + lr)*256 + lc;

    u64 acc[4][8];
    #pragma unroll
    for (int i = 0; i < 4; i++)
        #pragma unroll
        for (int j = 0; j < 8; j++) acc[i][j] = 0ull;

    for (int kb = 0; kb < 256; kb += 16){
        float4 a0 = *(const float4*)(Ap + kb);
        float4 a1 = *(const float4*)(Ap + (size_t)64*256 + kb);
        float4 b0 = *(const float4*)(Bp + kb);
        float4 b1 = *(const float4*)(Bp + (size_t)64*256 + kb);
        As[lc+0][lr]    = a0.x; As[lc+1][lr]    = a0.y; As[lc+2][lr]    = a0.z; As[lc+3][lr]    = a0.w;
        As[lc+0][lr+64] = a1.x; As[lc+1][lr+64] = a1.y; As[lc+2][lr+64] = a1.z; As[lc+3][lr+64] = a1.w;
        Bs[lc+0][lr]    = b0.x; Bs[lc+1][lr]    = b0.y; Bs[lc+2][lr]    = b0.z; Bs[lc+3][lr]    = b0.w;
        Bs[lc+0][lr+64] = b1.x; Bs[lc+1][lr+64] = b1.y; Bs[lc+2][lr+64] = b1.z; Bs[lc+3][lr+64] = b1.w;
        __syncthreads();
        #pragma unroll
        for (int k = 0; k < 16; k++){
            float4 av0 = *(const float4*)&As[k][ty*8];
            float4 av1 = *(const float4*)&As[k][ty*8+4];
            float4 bv0 = *(const float4*)&Bs[k][tx*8];
            float4 bv1 = *(const float4*)&Bs[k][tx*8+4];
            u64 ap[4] = { pk(av0.x,av0.y), pk(av0.z,av0.w), pk(av1.x,av1.y), pk(av1.z,av1.w) };
            u64 bd[8] = { pk(bv0.x,bv0.x), pk(bv0.y,bv0.y), pk(bv0.z,bv0.z), pk(bv0.w,bv0.w),
                          pk(bv1.x,bv1.x), pk(bv1.y,bv1.y), pk(bv1.z,bv1.z), pk(bv1.w,bv1.w) };
            #pragma unroll
            for (int i = 0; i < 4; i++)
                #pragma unroll
                for (int j = 0; j < 8; j++) fma2(acc[i][j], ap[i], bd[j]);
        }
        __syncthreads();
    }

    float bv[8];
    #pragma unroll
    for (int j = 0; j < 8; j++) bv[j] = __ldg(&bias[n0 + tx*8 + j]);
    #pragma unroll
    for (int i = 0; i < 4; i++){
        float c0[8], c1[8];
        #pragma unroll
        for (int j = 0; j < 8; j++){
            float2 f = up(acc[i][j]);
            c0[j] = f.x + bv[j];
            c1[j] = f.y + bv[j];
        }
        float* Cp0 = C + (size_t)(m0 + ty*8 + 2*i)*N + n0 + tx*8;
        float* Cp1 = Cp0 + N;
        ((float4*)Cp0)[0] = make_float4(c0[0],c0[1],c0[2],c0[3]);
        ((float4*)Cp0)[1] = make_float4(c0[4],c0[5],c0[6],c0[7]);
        ((float4*)Cp1)[0] = make_float4(c1[0],c1[1],c1[2],c1[3]);
        ((float4*)Cp1)[1] = make_float4(c1[4],c1[5],c1[6],c1[7]);
    }
}

// ---------------- per-layer scan state reset ----------------
__global__ void scan_init(){
    int i = blockIdx.x*256 + threadIdx.x;
    if (i < 2*B_*D_) g_hbuf[i] = 0.f;
    if (i < 16)      g_ctr[i]  = 0;
}

// ---------------- recurrent scan ----------------
// grid 128 = 16 batch-groups (4 batch) x 8 d-groups (32 dims -> 96 Wh rows).
// 192 threads: tid%96 = row, tid/96 = k-half (k-split-2).
#define SCAN_SMEM_BYTES ((24576 + 1024 + 384 + 96 + 32)*4)

__global__ __launch_bounds__(192,1)
void gru_scan(const float* __restrict__ Wh, const float* __restrict__ bh, int dsel){
    extern __shared__ float sm[];
    float* WHS = sm;                 // [(k4*96+rr)*4 + c]
    float* HS  = sm + 24576;         // [k*4 + b]
    float* GH  = sm + 24576 + 1024;  // [rr*4 + b]
    float* BH  = GH + 384;           // [96]

    float* out = dsel ? g_seqB : g_seqA;
    const int tid = threadIdx.x;
    const int bg  = blockIdx.x >> 3, dg = blockIdx.x & 7;

    for (int idx = tid; idx < 96*64; idx += 192){
        int rr = idx >> 6, k4 = idx & 63;
        int grow = (rr >> 5)*256 + dg*32 + (rr & 31);
        *(float4*)&WHS[(k4*96 + rr)*4] = *(const float4*)&Wh[(size_t)grow*256 + k4*4];
    }
    if (tid < 96) BH[tid] = bh[(tid >> 5)*256 + dg*32 + (tid & 31)];

    const int  rr = tid % 96, kh = tid / 96;
    const int  gb = tid >> 5, gd = tid & 31;
    const bool isGate = tid < 128;
    const size_t giBase  = (size_t)(bg*4 + gb)*S_*G3 + dg*32 + gd;
    const size_t hOff    = (size_t)(bg*4 + gb)*D_   + dg*32 + gd;
    const size_t outBase = (size_t)(bg*4 + gb)*S_*D_ + dg*32 + gd;
    __syncthreads();

    for (int t = 0; t < S_; t++){
        const int cur = t & 1;
        const float* hb = g_hbuf + cur*(B_*D_);
        #pragma unroll
        for (int i = 0; i < 6; i++){
            int idx = tid + i*192;
            if (idx < 1024){
                int b = idx >> 8, k = idx & 255;
                HS[k*4 + b] = __ldcg(&hb[(bg*4 + b)*D_ + k]);
            }
        }
        float gir = 0.f, giz = 0.f, gin = 0.f;
        if (isGate){
            const float* gp = g_gi + giBase + (size_t)t*G3;
            gir = __ldg(gp); giz = __ldg(gp + D_); gin = __ldg(gp + 2*D_);
        }
        __syncthreads();

        u64 a01 = 0ull, a23 = 0ull;
        const float4* wp = (const float4*)WHS + (size_t)kh*32*96 + rr;
        const float4* hp = (const float4*)HS + kh*128;
        #pragma unroll 8
        for (int k4 = 0; k4 < 32; k4++){
            float4 w  = wp[(size_t)k4*96];
            float4 hA = hp[k4*4+0], hB = hp[k4*4+1], hC = hp[k4*4+2], hD = hp[k4*4+3];
            u64 w0 = pk(w.x,w.x), w1 = pk(w.y,w.y), w2 = pk(w.z,w.z), w3 = pk(w.w,w.w);
            fma2(a01, w0, pk(hA.x,hA.y));  fma2(a23, w0, pk(hA.z,hA.w));
            fma2(a01, w1, pk(hB.x,hB.y));  fma2(a23, w1, pk(hB.z,hB.w));
            fma2(a01, w2, pk(hC.x,hC.y));  fma2(a23, w2, pk(hC.z,hC.w));
            fma2(a01, w3, pk(hD.x,hD.y));  fma2(a23, w3, pk(hD.z,hD.w));
        }
        if (kh){
            float2 p = up(a01), q = up(a23);
            *(float4*)&GH[rr*4] = make_float4(p.x, p.y, q.x, q.y);
        }
        __syncthreads();
        if (!kh){
            float4 o = *(float4*)&GH[rr*4];
            float2 p = up(a01), q = up(a23);
            float bb = BH[rr];
            o.x += p.x + bb; o.y += p.y + bb; o.z += q.x + bb; o.w += q.y + bb;
            *(float4*)&GH[rr*4] = o;
        }
        __syncthreads();

        if (isGate){
            float ghr = GH[gd*4 + gb];
            float ghz = GH[(32 + gd)*4 + gb];
            float ghn = GH[(64 + gd)*4 + gb];
            float hold = HS[(dg*32 + gd)*4 + gb];
            float r = 1.f/(1.f + __expf(-(gir + ghr)));
            float z = 1.f/(1.f + __expf(-(giz + ghz)));
            float n = tanhf(gin + r*ghn);
            float hn = (1.f - z)*n + z*hold;
            __stcg(&g_hbuf[(cur ^ 1)*(B_*D_) + hOff], hn);
            out[outBase + (size_t)t*D_] = hn;
        }
        __threadfence();
        if (tid == 0){
            atomicAdd(&g_ctr[bg], 1);
            const int tgt = (t + 1)*8;
            while (atomicAdd(&g_ctr[bg], 0) < tgt) __nanosleep(64);
            __threadfence();
        }
        __syncthreads();
    }
}

// ---------------- launch ----------------
extern "C" void kernel_launch(void* const* d_in, const int* in_sizes, int n_in,
                              void* d_out, int out_size){
    const int*   x     = (const int*)  d_in[0];
    const float* emb   = (const float*)d_in[1];
    const float* W_ih  = (const float*)d_in[2];
    const float* W_hh  = (const float*)d_in[3];
    const float* b_ih  = (const float*)d_in[4];
    const float* b_hh  = (const float*)d_in[5];
    const float* W_out = (const float*)d_in[6];
    const float* b_out = (const float*)d_in[7];
    float* out = (float*)d_out;

    static bool attr_done = false;
    if (!attr_done){
        cudaFuncSetAttribute(gru_scan, cudaFuncAttributeMaxDynamicSharedMemorySize,
                             SCAN_SMEM_BYTES);
        attr_done = true;
    }

    embed_k<<<(M_*64)/256, 256>>>(x, emb);

    for (int l = 0; l < L_; l++){
        int asel = l & 1;              // layer input buffer: A,B,A,B
        // input-side gates: [M,768] = seq * W_ih[l]^T + b_ih[l]
        gemm_tn<<<(M_/128)*(G3/128), 256>>>(asel, W_ih + (size_t)l*G3*D_,
                                            b_ih + (size_t)l*G3, nullptr, 0, G3);
        scan_init<<<(2*B_*D_)/256, 256>>>();
        gru_scan<<<128, 192, SCAN_SMEM_BYTES>>>(W_hh + (size_t)l*G3*D_,
                                                b_hh + (size_t)l*G3, asel ^ 1);
    }
    // logits: [M,256] = seq(A) * W_out^T + b_out  (after 4 layers seq is in A)
    gemm_tn<<<(M_/128)*(V_/128), 256>>>(0, W_out, b_out, out, 1, V_);
}